// round 4
// baseline (speedup 1.0000x reference)
#include <cuda_runtime.h>
#include <cstdint>

#define NUM_CLASSES 10
#define NBATCH 4
#define PER_BATCH 4096000        // 160^3 elements per batch
#define PB4 (PER_BATCH / 4)      // 1,024,000 int4 per batch
#define TPB 256
#define NWARP (TPB / 32)
#define GRIDX 296                // 296*4 = 1184 blocks = 148 SMs * 8 blocks -> one full wave
#define NBLOCKS (GRIDX * NBATCH)
#define ROWS 25                  // 100 keys -> 25 words of 4 byte-counters per lane

__device__ int g_hist[NBATCH * 100];   // pair histogram H[n][p*10 + t]; reset by last block
__device__ int g_done = 0;             // arrival ticket; reset by last block

// Conflict-free per-thread byte histogram:
// counter k of (warp w, lane l) at byte  w*3200 + (k>>2)*128 + l*4 + (k&3).
// word index = w*800 + (k>>2)*32 + l  ->  bank = l  (always), zero conflicts.
__global__ __launch_bounds__(TPB, 8) void dice_fused_kernel(const int4* __restrict__ yp,
                                                            const int4* __restrict__ yt,
                                                            float* __restrict__ out) {
    __shared__ unsigned char h8[NWARP * ROWS * 128];
    __shared__ unsigned int wsum[NWARP][ROWS][2];
    __shared__ float s_pred[NBATCH * 10];
    __shared__ float s_true[NBATCH * 10];
    __shared__ float s_int[NBATCH * 10];
    __shared__ int s_last;

    const int tid  = threadIdx.x;
    const int lane = tid & 31;
    const int w    = tid >> 5;
    unsigned char* my = h8 + (w * ROWS * 128 + lane * 4);

    // zero private counters (thread-private: no sync needed before use)
    #pragma unroll
    for (int r = 0; r < ROWS; r++)
        *reinterpret_cast<unsigned int*>(my + r * 128) = 0u;

    const int batch = blockIdx.y;
    const int4* __restrict__ p = yp + (size_t)batch * PB4;
    const int4* __restrict__ t = yt + (size_t)batch * PB4;

    const int stride = GRIDX * TPB;
    #pragma unroll 4
    for (int i = blockIdx.x * TPB + tid; i < PB4; i += stride) {
        int4 a = __ldcs(p + i);
        int4 b = __ldcs(t + i);
        int k0 = a.x * 10 + b.x;  my[((k0 & 124) << 5) + (k0 & 3)]++;
        int k1 = a.y * 10 + b.y;  my[((k1 & 124) << 5) + (k1 & 3)]++;
        int k2 = a.z * 10 + b.z;  my[((k2 & 124) << 5) + (k2 & 3)]++;
        int k3 = a.w * 10 + b.w;  my[((k3 & 124) << 5) + (k3 & 3)]++;
    }
    // max per-thread count: ceil(PB4/(GRIDX*TPB)) = 14 int4 = 56 elements <= 255: no overflow

    // Flush: byte-split each word (keys 4r..4r+3) into 16-bit fields, warp-reduce.
    #pragma unroll
    for (int r = 0; r < ROWS; r++) {
        unsigned int word = *reinterpret_cast<unsigned int*>(my + r * 128);
        unsigned int e0 = word & 0x00FF00FFu;          // keys 4r+0 (lo16), 4r+2 (hi16)
        unsigned int e1 = (word >> 8) & 0x00FF00FFu;   // keys 4r+1 (lo16), 4r+3 (hi16)
        unsigned int s0 = __reduce_add_sync(0xFFFFFFFFu, e0);  // <= 32*56 per field: no carry
        unsigned int s1 = __reduce_add_sync(0xFFFFFFFFu, e1);
        if (lane == 0) { wsum[w][r][0] = s0; wsum[w][r][1] = s1; }
    }
    __syncthreads();

    if (tid < 100) {
        int r = tid >> 2, b = tid & 3;
        int sh = (b >> 1) * 16, h = b & 1;
        unsigned int sum = 0;
        #pragma unroll
        for (int ww = 0; ww < NWARP; ww++)
            sum += (wsum[ww][r][h] >> sh) & 0xFFFFu;
        atomicAdd(&g_hist[batch * 100 + tid], (int)sum);
    }
    __syncthreads();

    // ---- last-block-done finalize (fused, saves a kernel launch) ----
    if (tid == 0) {
        __threadfence();                       // make this block's g_hist adds visible
        s_last = (atomicAdd(&g_done, 1) == NBLOCKS - 1);
        if (s_last) __threadfence();           // acquire side: see all blocks' adds
    }
    __syncthreads();
    if (!s_last) return;

    if (tid < NBATCH * 10) {
        int n = tid / 10, c = tid % 10;
        int cp = 0, ct = 0;
        #pragma unroll
        for (int k = 0; k < 10; k++) {
            cp += g_hist[n * 100 + c * 10 + k];   // sum over true labels  -> c_pred[n][c]
            ct += g_hist[n * 100 + k * 10 + c];   // sum over pred labels  -> c_true[n][c]
        }
        s_pred[tid] = (float)cp;
        s_true[tid] = (float)ct;
        s_int[tid]  = (float)g_hist[n * 100 + c * 10 + c];
    }
    __syncthreads();   // all g_hist reads complete before reset below

    // reset globals for the next graph replay (deterministic across replays)
    for (int i = tid; i < NBATCH * 100; i += TPB) g_hist[i] = 0;
    if (tid == 0) g_done = 0;

    if (tid == 0) {
        float loss = 1.0f;
        for (int n = 0; n < NBATCH; n++) {
            float tsum = 0.0f;
            for (int c = 1; c < NUM_CLASSES; c++) tsum += s_true[n * 10 + c];
            for (int c = 1; c < NUM_CLASSES; c++) {
                float cp = s_pred[n * 10 + c];
                float ct = s_true[n * 10 + c];
                float denom = cp + ct;
                if (denom > 0.0f) {
                    float dice = 2.0f * s_int[n * 10 + c] / denom;
                    float wgt = ct / tsum / (float)NBATCH;
                    loss -= wgt * dice;
                }
            }
        }
        out[0] = loss;
    }
}

extern "C" void kernel_launch(void* const* d_in, const int* in_sizes, int n_in,
                              void* d_out, int out_size) {
    const int4* yp = (const int4*)d_in[0];
    const int4* yt = (const int4*)d_in[1];

    dim3 grid(GRIDX, NBATCH);
    dice_fused_kernel<<<grid, TPB>>>(yp, yt, (float*)d_out);
}

// round 5
// speedup vs baseline: 1.1882x; 1.1882x over previous
#include <cuda_runtime.h>
#include <cstdint>

#define NUM_CLASSES 10
#define NBATCH 4
#define PER_BATCH 4096000        // 160^3 elements per batch
#define PB4 (PER_BATCH / 4)      // 1,024,000 int4 per batch
#define TPB 256
#define NWARP (TPB / 32)
#define GRIDX 148                // 148*4 batches = 592 blocks = 148 SMs * 4 blocks -> one wave
#define NBLOCKS (GRIDX * NBATCH)
#define ROWS 25                  // 100 keys -> 25 words of 4 byte-counters per lane

__device__ int g_hist[NBATCH * 100];   // pair histogram H[n][p*10 + t]; reset by last block
__device__ int g_done = 0;             // arrival ticket; reset by last block

// Conflict-free per-thread byte histogram:
// counter k of (warp w, lane l) at byte  w*3200 + (k>>2)*128 + l*4 + (k&3).
// word index = w*800 + (k>>2)*32 + l  ->  bank = l  (always), zero conflicts.
#define INC4(a, b)                                              \
    do {                                                        \
        int k0 = (a).x * 10 + (b).x;  my[((k0 & 124) << 5) + (k0 & 3)]++; \
        int k1 = (a).y * 10 + (b).y;  my[((k1 & 124) << 5) + (k1 & 3)]++; \
        int k2 = (a).z * 10 + (b).z;  my[((k2 & 124) << 5) + (k2 & 3)]++; \
        int k3 = (a).w * 10 + (b).w;  my[((k3 & 124) << 5) + (k3 & 3)]++; \
    } while (0)

__global__ __launch_bounds__(TPB, 4) void dice_fused_kernel(const int4* __restrict__ yp,
                                                            const int4* __restrict__ yt,
                                                            float* __restrict__ out) {
    __shared__ unsigned char h8[NWARP * ROWS * 128];
    __shared__ unsigned int wsum[NWARP][ROWS][2];
    __shared__ float s_pred[NBATCH * 10];
    __shared__ float s_true[NBATCH * 10];
    __shared__ float s_int[NBATCH * 10];
    __shared__ int s_last;

    const int tid  = threadIdx.x;
    const int lane = tid & 31;
    const int w    = tid >> 5;
    unsigned char* my = h8 + (w * ROWS * 128 + lane * 4);

    // zero private counters (thread-private: no sync needed before use)
    #pragma unroll
    for (int r = 0; r < ROWS; r++)
        *reinterpret_cast<unsigned int*>(my + r * 128) = 0u;

    const int batch = blockIdx.y;
    const int4* __restrict__ p = yp + (size_t)batch * PB4;
    const int4* __restrict__ t = yt + (size_t)batch * PB4;

    const int stride = GRIDX * TPB;   // 37,888
    int i = blockIdx.x * TPB + tid;

    // Main loop: 8 independent LDG.128 issued up-front -> MLP_eff ~ 8,
    // then 16 independent byte-RMW chains on the bank-exclusive histogram.
    #pragma unroll 1
    for (; i + 3 * stride < PB4; i += 4 * stride) {
        int4 a0 = __ldcs(p + i);
        int4 b0 = __ldcs(t + i);
        int4 a1 = __ldcs(p + i + stride);
        int4 b1 = __ldcs(t + i + stride);
        int4 a2 = __ldcs(p + i + 2 * stride);
        int4 b2 = __ldcs(t + i + 2 * stride);
        int4 a3 = __ldcs(p + i + 3 * stride);
        int4 b3 = __ldcs(t + i + 3 * stride);
        INC4(a0, b0);
        INC4(a1, b1);
        INC4(a2, b2);
        INC4(a3, b3);
    }
    #pragma unroll 1
    for (; i < PB4; i += stride) {
        int4 a = __ldcs(p + i);
        int4 b = __ldcs(t + i);
        INC4(a, b);
    }
    // max per-thread count: ceil(PB4/(GRIDX*TPB)) = 28 int4 = 112 elements <= 255: no overflow

    // Flush: byte-split each word (keys 4r..4r+3) into 16-bit fields, warp-reduce.
    #pragma unroll
    for (int r = 0; r < ROWS; r++) {
        unsigned int word = *reinterpret_cast<unsigned int*>(my + r * 128);
        unsigned int e0 = word & 0x00FF00FFu;          // keys 4r+0 (lo16), 4r+2 (hi16)
        unsigned int e1 = (word >> 8) & 0x00FF00FFu;   // keys 4r+1 (lo16), 4r+3 (hi16)
        unsigned int s0 = __reduce_add_sync(0xFFFFFFFFu, e0);  // <= 32*112 per field: no carry
        unsigned int s1 = __reduce_add_sync(0xFFFFFFFFu, e1);
        if (lane == 0) { wsum[w][r][0] = s0; wsum[w][r][1] = s1; }
    }
    __syncthreads();

    if (tid < 100) {
        int r = tid >> 2, b = tid & 3;
        int sh = (b >> 1) * 16, h = b & 1;
        unsigned int sum = 0;
        #pragma unroll
        for (int ww = 0; ww < NWARP; ww++)
            sum += (wsum[ww][r][h] >> sh) & 0xFFFFu;
        atomicAdd(&g_hist[batch * 100 + tid], (int)sum);
    }
    __syncthreads();

    // ---- last-block-done finalize (fused, saves a kernel launch) ----
    if (tid == 0) {
        __threadfence();                       // make this block's g_hist adds visible
        s_last = (atomicAdd(&g_done, 1) == NBLOCKS - 1);
        if (s_last) __threadfence();           // acquire side: see all blocks' adds
    }
    __syncthreads();
    if (!s_last) return;

    if (tid < NBATCH * 10) {
        int n = tid / 10, c = tid % 10;
        int cp = 0, ct = 0;
        #pragma unroll
        for (int k = 0; k < 10; k++) {
            cp += g_hist[n * 100 + c * 10 + k];   // sum over true labels  -> c_pred[n][c]
            ct += g_hist[n * 100 + k * 10 + c];   // sum over pred labels  -> c_true[n][c]
        }
        s_pred[tid] = (float)cp;
        s_true[tid] = (float)ct;
        s_int[tid]  = (float)g_hist[n * 100 + c * 10 + c];
    }
    __syncthreads();   // all g_hist reads complete before reset below

    // reset globals for the next graph replay (deterministic across replays)
    for (int j = tid; j < NBATCH * 100; j += TPB) g_hist[j] = 0;
    if (tid == 0) g_done = 0;

    if (tid == 0) {
        float loss = 1.0f;
        for (int n = 0; n < NBATCH; n++) {
            float tsum = 0.0f;
            for (int c = 1; c < NUM_CLASSES; c++) tsum += s_true[n * 10 + c];
            for (int c = 1; c < NUM_CLASSES; c++) {
                float cp = s_pred[n * 10 + c];
                float ct = s_true[n * 10 + c];
                float denom = cp + ct;
                if (denom > 0.0f) {
                    float dice = 2.0f * s_int[n * 10 + c] / denom;
                    float wgt = ct / tsum / (float)NBATCH;
                    loss -= wgt * dice;
                }
            }
        }
        out[0] = loss;
    }
}

extern "C" void kernel_launch(void* const* d_in, const int* in_sizes, int n_in,
                              void* d_out, int out_size) {
    const int4* yp = (const int4*)d_in[0];
    const int4* yt = (const int4*)d_in[1];

    dim3 grid(GRIDX, NBATCH);
    dice_fused_kernel<<<grid, TPB>>>(yp, yt, (float*)d_out);
}